// round 7
// baseline (speedup 1.0000x reference)
#include <cuda_runtime.h>
#include <cuda_bf16.h>
#include <math.h>
#include <stdint.h>
#include <stddef.h>

// ---------------- problem constants ----------------
constexpr int NB   = 8;     // batch
constexpr int LSEQ = 256;   // encoder seq len
constexpr int NLAY = 4;     // layers per stack
constexpr int DM   = 384;   // model dim
constexpr int DKK  = 384;   // qkv dim
constexpr int NH   = 2;     // heads
constexpr int DS   = 192;   // head dim
constexpr int CDIM = 1536;  // conv hidden
constexpr int MMEL = 80;    // mel bins
constexpr int TMAX = 3840;  // max possible expanded length (256 * 15)
constexpr long RMAX = (long)NB * TMAX;   // 30720 max rows

// ---------------- static scratch (no runtime allocation allowed) ----------------
__device__ float g_x  [RMAX * DM];             // activations (enc, then reused)
__device__ float g_x2 [RMAX * DM];             // decoder activations
__device__ float g_q  [RMAX * DKK];
__device__ float g_k  [RMAX * DKK];
__device__ float g_v  [RMAX * DKK];
__device__ float g_z  [RMAX * DKK];
__device__ float g_t  [RMAX * DM];             // temp (attn out / conv2 out)
__device__ float g_h  [RMAX * CDIM];           // conv hidden
__device__ float g_sc [(size_t)NB * NH * TMAX * TMAX];  // scores (B*H, S, S)
__device__ int   g_idx[RMAX];                  // length-regulator gather map
// transposed conv weights: [stack(2)][layer][tap][Cin][Cout]
__device__ float g_c1wT[2 * NLAY * 3 * DM * CDIM];
__device__ float g_c2wT[2 * NLAY * 3 * CDIM * DM];

// ---------------- helpers ----------------
__device__ __forceinline__ float pe_val(int b, int d) {
    int i2 = (d >> 1) << 1;
    float div = expf(-(float)i2 * (9.210340371976184f / (float)DM)); // ln(10000)/D
    float ang = (float)b * div;
    return (d & 1) ? cosf(ang) : sinf(ang);
}

// split v0,v1 into packed bf16x2 hi and lo parts
__device__ __forceinline__ void split_pack(float v0, float v1,
                                           uint32_t& hi, uint32_t& lo) {
    __nv_bfloat16 h0 = __float2bfloat16(v0);
    __nv_bfloat16 h1 = __float2bfloat16(v1);
    __nv_bfloat16 l0 = __float2bfloat16(v0 - __bfloat162float(h0));
    __nv_bfloat16 l1 = __float2bfloat16(v1 - __bfloat162float(h1));
    __nv_bfloat162 hp; hp.x = h0; hp.y = h1;
    __nv_bfloat162 lp; lp.x = l0; lp.y = l1;
    hi = *reinterpret_cast<uint32_t*>(&hp);
    lo = *reinterpret_cast<uint32_t*>(&lp);
}

// x[b,s,:] = emb[tokens[b,s],:] + pe[b,:]
__global__ void embed_kernel(const int* __restrict__ tokens,
                             const float* __restrict__ emb,
                             float* __restrict__ x) {
    int i = blockIdx.x * blockDim.x + threadIdx.x;
    const int tot = NB * LSEQ * DM;
    if (i >= tot) return;
    int d  = i % DM;
    int bs = i / DM;
    int b  = bs / LSEQ;
    int tok = tokens[bs];
    x[i] = emb[tok * DM + d] + pe_val(b, d);
}

// w: (layers, Cout, Cin, 3)  ->  wt: (layers, 3, Cin, Cout)
__global__ void transpose_w_kernel(const float* __restrict__ w,
                                   float* __restrict__ wt,
                                   int Cout, int Cin, int layers) {
    size_t tot = (size_t)layers * Cout * Cin * 3;
    for (size_t idx = (size_t)blockIdx.x * blockDim.x + threadIdx.x;
         idx < tot; idx += (size_t)gridDim.x * blockDim.x) {
        int t = (int)(idx % 3);
        size_t r = idx / 3;
        int d = (int)(r % Cin);
        size_t r2 = r / Cin;
        int c = (int)(r2 % Cout);
        int l = (int)(r2 / Cout);
        wt[(((size_t)l * 3 + t) * Cin + d) * Cout + c] = w[idx];
    }
}

// softmax across the 16 (B*H) slices for every (i,j)
__global__ void softmax_g_kernel(float* __restrict__ sc, int S) {
    size_t ij = (size_t)blockIdx.x * blockDim.x + threadIdx.x;
    size_t tot = (size_t)S * S;
    if (ij >= tot) return;
    float v[NB * NH];
    float m = -1e30f;
#pragma unroll
    for (int g = 0; g < NB * NH; g++) {
        v[g] = sc[(size_t)g * tot + ij];
        m = fmaxf(m, v[g]);
    }
    float s = 0.f;
#pragma unroll
    for (int g = 0; g < NB * NH; g++) { v[g] = expf(v[g] - m); s += v[g]; }
    float inv = 1.f / s;
#pragma unroll
    for (int g = 0; g < NB * NH; g++) sc[(size_t)g * tot + ij] = v[g] * inv;
}

// x = LayerNorm(x + y) * gamma + beta   (row length DM=384, one warp per row)
__global__ void ln_res_kernel(float* __restrict__ x, const float* __restrict__ y,
                              const float* __restrict__ gamma,
                              const float* __restrict__ beta, int Mrows) {
    int warp = (blockIdx.x * blockDim.x + threadIdx.x) >> 5;
    int lane = threadIdx.x & 31;
    if (warp >= Mrows) return;
    const float* xr = x + (size_t)warp * DM;
    const float* yr = y + (size_t)warp * DM;
    float vals[DM / 32];
    float s = 0.f;
#pragma unroll
    for (int i = 0; i < DM / 32; i++) {
        int d = lane + i * 32;
        vals[i] = xr[d] + yr[d];
        s += vals[i];
    }
#pragma unroll
    for (int o = 16; o > 0; o >>= 1) s += __shfl_xor_sync(0xffffffffu, s, o);
    float mean = s / (float)DM;
    float vs = 0.f;
#pragma unroll
    for (int i = 0; i < DM / 32; i++) { float t = vals[i] - mean; vs += t * t; }
#pragma unroll
    for (int o = 16; o > 0; o >>= 1) vs += __shfl_xor_sync(0xffffffffu, vs, o);
    float inv = rsqrtf(vs / (float)DM + 1e-5f);
    float* xw = x + (size_t)warp * DM;
#pragma unroll
    for (int i = 0; i < DM / 32; i++) {
        int d = lane + i * 32;
        xw[d] = (vals[i] - mean) * inv * gamma[d] + beta[d];
    }
}

// per-batch prefix sum over durations -> idx[b,t] = source token (or -1)
__global__ void scan_kernel(const int* __restrict__ target, int* __restrict__ idx, int T) {
    __shared__ int sdur[LSEQ];
    __shared__ int soff[LSEQ + 1];
    int b = blockIdx.x;
    int j = threadIdx.x;
    sdur[j] = target[b * LSEQ + j];
    __syncthreads();
    if (j == 0) {
        int acc = 0;
        for (int kk = 0; kk < LSEQ; kk++) { soff[kk] = acc; acc += sdur[kk]; }
        soff[LSEQ] = acc;
    }
    __syncthreads();
    int st = soff[j];
    int en = st + sdur[j];
    for (int t = st; t < en; t++) idx[b * T + t] = j;
    int total = soff[LSEQ];
    for (int t = total + j; t < T; t += LSEQ) idx[b * T + t] = -1;
}

// xd[b,t,:] = (idx>=0 ? xe[b,idx,:] : 0) + pe[b,:]
__global__ void gather_pe_kernel(const float* __restrict__ xe,
                                 const int* __restrict__ idx,
                                 float* __restrict__ xd, int T) {
    size_t i = (size_t)blockIdx.x * blockDim.x + threadIdx.x;
    size_t tot = (size_t)NB * T * DM;
    if (i >= tot) return;
    int d = (int)(i % DM);
    size_t bt = i / DM;
    int b = (int)(bt / T);
    int j = idx[bt];
    float val = (j >= 0) ? xe[((size_t)b * LSEQ + j) * DM + d] : 0.f;
    xd[i] = val + pe_val(b, d);
}

// ---------------- m16n8k16 bf16 mma wrapper ----------------
__device__ __forceinline__ void mma_bf16(float* c, const uint32_t* a, const uint32_t* b) {
    asm volatile(
        "mma.sync.aligned.m16n8k16.row.col.f32.bf16.bf16.f32 "
        "{%0,%1,%2,%3}, {%4,%5,%6,%7}, {%8,%9}, {%0,%1,%2,%3};"
        : "+f"(c[0]), "+f"(c[1]), "+f"(c[2]), "+f"(c[3])
        : "r"(a[0]), "r"(a[1]), "r"(a[2]), "r"(a[3]),
          "r"(b[0]), "r"(b[1]));
}

// ---------------- generic 128x128x16 bf16x3 tensor-core GEMM ----------------
// Error-compensated: x = hi + lo (bf16 split); A@B ~= Ah@Bh + Ah@Bl + Al@Bh.
// mode 0: C = act(A@B + bias)        A(M,K) lda, B(K,N) ldb row-major
// mode 1: scores: per g=blockIdx.z  C[g] = scale * Q[g] @ K[g]^T  (B transposed access)
// mode 2: AV:     per g             C[g](S,DS) = attn[g] @ V[g], strided C (merge heads)
// mode 3: conv3:  C = relu(sum_tap Xshift(tap) @ Wt + bias), K = 3*Cin
// 8 warps: 2 (m) x 4 (n); warp tile 64x32 = 4x4 tiles of m16n8; BK=16 = one k16 step.
// Smem holds k in packed pairs: As_*[pair(8)][m(128+pad)], bf16x2 per entry.
__global__ void __launch_bounds__(256, 2)
gemm_kernel(int mode,
            const float* __restrict__ A, int lda,
            const float* __restrict__ Bm, int ldb,
            const float* __restrict__ bias,
            float* __restrict__ C, int ldc,
            int M, int N, int K, float scale, int relu,
            int S, int Cin) {
    __shared__ uint32_t As_hi[8][132];
    __shared__ uint32_t As_lo[8][132];
    __shared__ uint32_t Bs_hi[8][132];
    __shared__ uint32_t Bs_lo[8][132];
    int tid = threadIdx.x;
    int row0 = blockIdx.y * 128;
    int col0 = blockIdx.x * 128;
    int g = blockIdx.z;
    if (mode == 1) {
        int b = g >> 1, h = g & 1;
        A  += (size_t)b * S * 384 + h * DS;
        Bm += (size_t)b * S * 384 + h * DS;
        C  += (size_t)g * S * S;
    } else if (mode == 2) {
        int b = g >> 1, h = g & 1;
        A  += (size_t)g * S * S;
        Bm += (size_t)b * S * 384 + h * DS;
        C  += (size_t)b * S * 384 + h * DS;
    }

    int wid  = tid >> 5;
    int lane = tid & 31;
    int wm = (wid & 1) * 64;      // warp row offset within 128
    int wn = (wid >> 1) * 32;     // warp col offset within 128
    int gid = lane >> 2;          // 0..7
    int tig = lane & 3;           // 0..3

    float acc[16][4];             // [i*4+j][c0..c3]
#pragma unroll
    for (int t = 0; t < 16; t++)
#pragma unroll
        for (int c = 0; c < 4; c++) acc[t][c] = 0.f;

    for (int k0 = 0; k0 < K; k0 += 16) {
        // ---- load A tile: thread handles pair (2 consecutive k) for row m ----
#pragma unroll
        for (int it = 0; it < 4; it++) {
            int idx = tid + it * 256;          // 0..1023
            int pair = idx & 7;                // k-pair 0..7
            int m = idx >> 3;                  // 0..127
            int r = row0 + m;
            int kg0 = k0 + pair * 2;
            float v0 = 0.f, v1 = 0.f;
            if (mode == 3) {
                if (r < M) {
                    int b = r / S, s = r - b * S;
                    if (kg0 < K) {
                        int tap = kg0 / Cin, d = kg0 - tap * Cin;
                        int ss = s + tap - 1;
                        if (ss >= 0 && ss < S) v0 = A[((size_t)b * S + ss) * Cin + d];
                    }
                    if (kg0 + 1 < K) {
                        int kg1 = kg0 + 1;
                        int tap = kg1 / Cin, d = kg1 - tap * Cin;
                        int ss = s + tap - 1;
                        if (ss >= 0 && ss < S) v1 = A[((size_t)b * S + ss) * Cin + d];
                    }
                }
            } else {
                if (r < M) {
                    const float* ar = A + (size_t)r * lda;
                    if (kg0 < K)     v0 = ar[kg0];
                    if (kg0 + 1 < K) v1 = ar[kg0 + 1];
                }
            }
            split_pack(v0, v1, As_hi[pair][m], As_lo[pair][m]);
        }
        // ---- load B tile (Bs[pair][n]) ----
        if (mode == 1) {
            // B accessed transposed: row c, consecutive kg -> contiguous loads
#pragma unroll
            for (int it = 0; it < 4; it++) {
                int idx = tid + it * 256;
                int pair = idx & 7;
                int n = idx >> 3;
                int c = col0 + n;
                int kg0 = k0 + pair * 2;
                float v0 = 0.f, v1 = 0.f;
                if (c < N) {
                    const float* br = Bm + (size_t)c * ldb;
                    if (kg0 < K)     v0 = br[kg0];
                    if (kg0 + 1 < K) v1 = br[kg0 + 1];
                }
                split_pack(v0, v1, Bs_hi[pair][n], Bs_lo[pair][n]);
            }
        } else {
            // B row-major (K,N): consecutive threads -> consecutive n, coalesced
#pragma unroll
            for (int it = 0; it < 4; it++) {
                int idx = tid + it * 256;
                int n = idx & 127;
                int pair = idx >> 7;
                int c = col0 + n;
                int kg0 = k0 + pair * 2;
                float v0 = 0.f, v1 = 0.f;
                if (c < N) {
                    if (kg0 < K)     v0 = Bm[(size_t)kg0 * ldb + c];
                    if (kg0 + 1 < K) v1 = Bm[(size_t)(kg0 + 1) * ldb + c];
                }
                split_pack(v0, v1, Bs_hi[pair][n], Bs_lo[pair][n]);
            }
        }
        __syncthreads();
        // ---- compute: one k16 step, 3 compensated products ----
        {
            uint32_t a_hi[4][4], b_hi[4][2];
#pragma unroll
            for (int i = 0; i < 4; i++) {
                int m0 = wm + i * 16 + gid;
                a_hi[i][0] = As_hi[tig][m0];
                a_hi[i][1] = As_hi[tig][m0 + 8];
                a_hi[i][2] = As_hi[tig + 4][m0];
                a_hi[i][3] = As_hi[tig + 4][m0 + 8];
            }
#pragma unroll
            for (int j = 0; j < 4; j++) {
                int n0 = wn + j * 8 + gid;
                b_hi[j][0] = Bs_hi[tig][n0];
                b_hi[j][1] = Bs_hi[tig + 4][n0];
            }
            // hi * hi
#pragma unroll
            for (int i = 0; i < 4; i++)
#pragma unroll
                for (int j = 0; j < 4; j++)
                    mma_bf16(acc[i * 4 + j], a_hi[i], b_hi[j]);
            // hi * lo
            {
                uint32_t b_lo[4][2];
#pragma unroll
                for (int j = 0; j < 4; j++) {
                    int n0 = wn + j * 8 + gid;
                    b_lo[j][0] = Bs_lo[tig][n0];
                    b_lo[j][1] = Bs_lo[tig + 4][n0];
                }
#pragma unroll
                for (int i = 0; i < 4; i++)
#pragma unroll
                    for (int j = 0; j < 4; j++)
                        mma_bf16(acc[i * 4 + j], a_hi[i], b_lo[j]);
            }
            // lo * hi
            {
                uint32_t a_lo[4][4];
#pragma unroll
                for (int i = 0; i < 4; i++) {
                    int m0 = wm + i * 16 + gid;
                    a_lo[i][0] = As_lo[tig][m0];
                    a_lo[i][1] = As_lo[tig][m0 + 8];
                    a_lo[i][2] = As_lo[tig + 4][m0];
                    a_lo[i][3] = As_lo[tig + 4][m0 + 8];
                }
#pragma unroll
                for (int i = 0; i < 4; i++)
#pragma unroll
                    for (int j = 0; j < 4; j++)
                        mma_bf16(acc[i * 4 + j], a_lo[i], b_hi[j]);
            }
        }
        __syncthreads();
    }

    // ---- epilogue ----
#pragma unroll
    for (int i = 0; i < 4; i++) {
#pragma unroll
        for (int j = 0; j < 4; j++) {
            float* c4 = acc[i * 4 + j];
            int cc = col0 + wn + j * 8 + tig * 2;
#pragma unroll
            for (int half = 0; half < 2; half++) {
                int r = row0 + wm + i * 16 + gid + half * 8;
                if (r >= M) continue;
#pragma unroll
                for (int e = 0; e < 2; e++) {
                    int c = cc + e;
                    if (c >= N) continue;
                    float v = c4[half * 2 + e] * scale;
                    if (bias) v += bias[c];
                    if (relu) v = fmaxf(v, 0.f);
                    C[(size_t)r * ldc + c] = v;
                }
            }
        }
    }
}

// ---------------- host driver ----------------
static inline void launch_gemm(int mode, const float* A, int lda,
                               const float* B, int ldb, const float* bias,
                               float* C, int ldc, int M, int N, int K,
                               float scale, int relu, int S, int Cin, int batch) {
    dim3 grid((N + 127) / 128, (M + 127) / 128, batch);
    gemm_kernel<<<grid, 256>>>(mode, A, lda, B, ldb, bias, C, ldc,
                               M, N, K, scale, relu, S, Cin);
}

extern "C" void kernel_launch(void* const* d_in, const int* in_sizes, int n_in,
                              void* d_out, int out_size) {
    // -------- input pointers (metadata order) --------
    const int*   tokens  = (const int*)d_in[0];
    const int*   target  = (const int*)d_in[1];
    const float* emb     = (const float*)d_in[2];
    const float* s_Wqkv[2] = { (const float*)d_in[3],  (const float*)d_in[13] };
    const float* s_bqkv[2] = { (const float*)d_in[4],  (const float*)d_in[14] };
    const float* s_Wo  [2] = { (const float*)d_in[5],  (const float*)d_in[15] };
    const float* s_bo  [2] = { (const float*)d_in[6],  (const float*)d_in[16] };
    const float* s_ln1 [2] = { (const float*)d_in[7],  (const float*)d_in[17] };
    const float* s_c1w [2] = { (const float*)d_in[8],  (const float*)d_in[18] };
    const float* s_c1b [2] = { (const float*)d_in[9],  (const float*)d_in[19] };
    const float* s_c2w [2] = { (const float*)d_in[10], (const float*)d_in[20] };
    const float* s_c2b [2] = { (const float*)d_in[11], (const float*)d_in[21] };
    const float* s_ln2 [2] = { (const float*)d_in[12], (const float*)d_in[22] };
    const float* head_w  = (const float*)d_in[23];
    const float* head_b  = (const float*)d_in[24];
    float* out = (float*)d_out;

    // -------- scratch pointers --------
    float *x, *x2, *q, *k, *v, *z, *tmp, *h, *sc, *c1wT, *c2wT;
    int* idxp;
    cudaGetSymbolAddress((void**)&x,    g_x);
    cudaGetSymbolAddress((void**)&x2,   g_x2);
    cudaGetSymbolAddress((void**)&q,    g_q);
    cudaGetSymbolAddress((void**)&k,    g_k);
    cudaGetSymbolAddress((void**)&v,    g_v);
    cudaGetSymbolAddress((void**)&z,    g_z);
    cudaGetSymbolAddress((void**)&tmp,  g_t);
    cudaGetSymbolAddress((void**)&h,    g_h);
    cudaGetSymbolAddress((void**)&sc,   g_sc);
    cudaGetSymbolAddress((void**)&idxp, g_idx);
    cudaGetSymbolAddress((void**)&c1wT, g_c1wT);
    cudaGetSymbolAddress((void**)&c2wT, g_c2wT);

    const int T = out_size / (NB * MMEL);   // expanded length from output shape

    // -------- weight transposes (conv weights -> (tap,Cin,Cout)) --------
    for (int st = 0; st < 2; st++) {
        transpose_w_kernel<<<2048, 256>>>(s_c1w[st],
            c1wT + (size_t)st * NLAY * 3 * DM * CDIM, CDIM, DM, NLAY);
        transpose_w_kernel<<<2048, 256>>>(s_c2w[st],
            c2wT + (size_t)st * NLAY * 3 * CDIM * DM, DM, CDIM, NLAY);
    }

    // -------- embedding + pe --------
    {
        int tot = NB * LSEQ * DM;
        embed_kernel<<<(tot + 255) / 256, 256>>>(tokens, emb, x);
    }

    const float attn_scale = rsqrtf((float)DS);

    // -------- run a stack (st = 0 enc, 1 dec) --------
    auto run_stack = [&](int st, float* xbuf, int S) {
        int Mr = NB * S;
        for (int l = 0; l < NLAY; l++) {
            const float* Wqkv = s_Wqkv[st] + (size_t)l * 3 * DM * DKK;
            const float* bqkv = s_bqkv[st] + (size_t)l * 3 * DKK;
            // q,k,v = relu(x @ Wqkv_t + b_t)
            launch_gemm(0, xbuf, DM, Wqkv + 0 * DM * DKK, DKK, bqkv + 0 * DKK,
                        q, DKK, Mr, DKK, DM, 1.f, 1, 0, 0, 1);
            launch_gemm(0, xbuf, DM, Wqkv + 1 * DM * DKK, DKK, bqkv + 1 * DKK,
                        k, DKK, Mr, DKK, DM, 1.f, 1, 0, 0, 1);
            launch_gemm(0, xbuf, DM, Wqkv + 2 * DM * DKK, DKK, bqkv + 2 * DKK,
                        v, DKK, Mr, DKK, DM, 1.f, 1, 0, 0, 1);
            // scores[g] = scale * q[g] @ k[g]^T
            launch_gemm(1, q, 384, k, 384, nullptr, sc, S,
                        S, S, DS, attn_scale, 0, S, 0, NB * NH);
            // softmax over g
            {
                size_t tot = (size_t)S * S;
                softmax_g_kernel<<<(unsigned)((tot + 255) / 256), 256>>>(sc, S);
            }
            // z[g] = attn[g] @ v[g]  (written merged into (B,S,384))
            launch_gemm(2, sc, S, v, 384, nullptr, z, 384,
                        S, DS, S, 1.f, 0, S, 0, NB * NH);
            // tmp = relu(z @ Wo + bo)
            launch_gemm(0, z, DKK, s_Wo[st] + (size_t)l * DKK * DM, DM,
                        s_bo[st] + (size_t)l * DM, tmp, DM,
                        Mr, DM, DKK, 1.f, 1, 0, 0, 1);
            // x = LN(x + tmp)
            ln_res_kernel<<<(Mr + 7) / 8, 256>>>(xbuf, tmp,
                s_ln1[st] + (size_t)(l * 2 + 0) * DM,
                s_ln1[st] + (size_t)(l * 2 + 1) * DM, Mr);
            // h = relu(conv1(x))
            launch_gemm(3, xbuf, DM,
                        c1wT + ((size_t)st * NLAY + l) * 3 * DM * CDIM, CDIM,
                        s_c1b[st] + (size_t)l * CDIM, h, CDIM,
                        Mr, CDIM, 3 * DM, 1.f, 1, S, DM, 1);
            // tmp = relu(conv2(h))
            launch_gemm(3, h, CDIM,
                        c2wT + ((size_t)st * NLAY + l) * 3 * CDIM * DM, DM,
                        s_c2b[st] + (size_t)l * DM, tmp, DM,
                        Mr, DM, 3 * CDIM, 1.f, 1, S, CDIM, 1);
            // x = LN(x + tmp)
            ln_res_kernel<<<(Mr + 7) / 8, 256>>>(xbuf, tmp,
                s_ln2[st] + (size_t)(l * 2 + 0) * DM,
                s_ln2[st] + (size_t)(l * 2 + 1) * DM, Mr);
        }
    };

    // encoder
    run_stack(0, x, LSEQ);

    // length regulator + pe
    scan_kernel<<<NB, LSEQ>>>(target, idxp, T);
    {
        size_t tot = (size_t)NB * T * DM;
        gather_pe_kernel<<<(unsigned)((tot + 255) / 256), 256>>>(x, idxp, x2, T);
    }

    // decoder
    run_stack(1, x2, T);

    // mel head: out = x2 @ head_w + head_b
    launch_gemm(0, x2, DM, head_w, MMEL, head_b, out, MMEL,
                NB * T, MMEL, DM, 1.f, 0, 0, 0, 1);
}

// round 8
// speedup vs baseline: 1.7351x; 1.7351x over previous
#include <cuda_runtime.h>
#include <cuda_bf16.h>
#include <math.h>
#include <stdint.h>
#include <stddef.h>

// ---------------- problem constants ----------------
constexpr int NB   = 8;     // batch
constexpr int LSEQ = 256;   // encoder seq len
constexpr int NLAY = 4;     // layers per stack
constexpr int DM   = 384;   // model dim
constexpr int DKK  = 384;   // qkv dim
constexpr int NH   = 2;     // heads
constexpr int DS   = 192;   // head dim
constexpr int CDIM = 1536;  // conv hidden
constexpr int MMEL = 80;    // mel bins
constexpr int TMAX = 3840;  // max possible expanded length (256 * 15)
constexpr long RMAX = (long)NB * TMAX;   // 30720 max rows
constexpr size_t QKV_STRIDE = (size_t)RMAX * DKK;

// ---------------- static scratch (no runtime allocation allowed) ----------------
__device__ float g_x  [RMAX * DM];             // activations (enc, then reused)
__device__ float g_x2 [RMAX * DM];             // decoder activations
__device__ float g_qkv[3 * RMAX * DKK];        // q,k,v contiguous (z-strided)
__device__ float g_z  [RMAX * DKK];
__device__ float g_t  [RMAX * DM];             // temp (attn out / conv2 out)
__device__ float g_h  [RMAX * CDIM];           // conv hidden
__device__ float g_sc [(size_t)NB * NH * TMAX * TMAX];  // scores (B*H, S, S)
__device__ int   g_idx[RMAX];                  // length-regulator gather map
// transposed conv weights: [stack(2)][layer][tap][Cin][Cout]
__device__ float g_c1wT[2 * NLAY * 3 * DM * CDIM];
__device__ float g_c2wT[2 * NLAY * 3 * CDIM * DM];

// ---------------- helpers ----------------
__device__ __forceinline__ float pe_val(int b, int d) {
    int i2 = (d >> 1) << 1;
    float div = expf(-(float)i2 * (9.210340371976184f / (float)DM)); // ln(10000)/D
    float ang = (float)b * div;
    return (d & 1) ? cosf(ang) : sinf(ang);
}

// split v0,v1 into packed bf16x2 hi and lo parts
__device__ __forceinline__ void split_pack(float v0, float v1,
                                           uint32_t& hi, uint32_t& lo) {
    __nv_bfloat16 h0 = __float2bfloat16(v0);
    __nv_bfloat16 h1 = __float2bfloat16(v1);
    __nv_bfloat16 l0 = __float2bfloat16(v0 - __bfloat162float(h0));
    __nv_bfloat16 l1 = __float2bfloat16(v1 - __bfloat162float(h1));
    __nv_bfloat162 hp; hp.x = h0; hp.y = h1;
    __nv_bfloat162 lp; lp.x = l0; lp.y = l1;
    hi = *reinterpret_cast<uint32_t*>(&hp);
    lo = *reinterpret_cast<uint32_t*>(&lp);
}

// x[b,s,:] = emb[tokens[b,s],:] + pe[b,:]
__global__ void embed_kernel(const int* __restrict__ tokens,
                             const float* __restrict__ emb,
                             float* __restrict__ x) {
    int i = blockIdx.x * blockDim.x + threadIdx.x;
    const int tot = NB * LSEQ * DM;
    if (i >= tot) return;
    int d  = i % DM;
    int bs = i / DM;
    int b  = bs / LSEQ;
    int tok = tokens[bs];
    x[i] = emb[tok * DM + d] + pe_val(b, d);
}

// w: (layers, Cout, Cin, 3)  ->  wt: (layers, 3, Cin, Cout)
__global__ void transpose_w_kernel(const float* __restrict__ w,
                                   float* __restrict__ wt,
                                   int Cout, int Cin, int layers) {
    size_t tot = (size_t)layers * Cout * Cin * 3;
    for (size_t idx = (size_t)blockIdx.x * blockDim.x + threadIdx.x;
         idx < tot; idx += (size_t)gridDim.x * blockDim.x) {
        int t = (int)(idx % 3);
        size_t r = idx / 3;
        int d = (int)(r % Cin);
        size_t r2 = r / Cin;
        int c = (int)(r2 % Cout);
        int l = (int)(r2 / Cout);
        wt[(((size_t)l * 3 + t) * Cin + d) * Cout + c] = w[idx];
    }
}

// softmax across the 16 (B*H) slices for every (i,j)
__global__ void softmax_g_kernel(float* __restrict__ sc, int S) {
    size_t ij = (size_t)blockIdx.x * blockDim.x + threadIdx.x;
    size_t tot = (size_t)S * S;
    if (ij >= tot) return;
    float v[NB * NH];
    float m = -1e30f;
#pragma unroll
    for (int g = 0; g < NB * NH; g++) {
        v[g] = sc[(size_t)g * tot + ij];
        m = fmaxf(m, v[g]);
    }
    float s = 0.f;
#pragma unroll
    for (int g = 0; g < NB * NH; g++) { v[g] = expf(v[g] - m); s += v[g]; }
    float inv = 1.f / s;
#pragma unroll
    for (int g = 0; g < NB * NH; g++) sc[(size_t)g * tot + ij] = v[g] * inv;
}

// x = LayerNorm(x + y) * gamma + beta   (row length DM=384, one warp per row)
__global__ void ln_res_kernel(float* __restrict__ x, const float* __restrict__ y,
                              const float* __restrict__ gamma,
                              const float* __restrict__ beta, int Mrows) {
    int warp = (blockIdx.x * blockDim.x + threadIdx.x) >> 5;
    int lane = threadIdx.x & 31;
    if (warp >= Mrows) return;
    const float* xr = x + (size_t)warp * DM;
    const float* yr = y + (size_t)warp * DM;
    float vals[DM / 32];
    float s = 0.f;
#pragma unroll
    for (int i = 0; i < DM / 32; i++) {
        int d = lane + i * 32;
        vals[i] = xr[d] + yr[d];
        s += vals[i];
    }
#pragma unroll
    for (int o = 16; o > 0; o >>= 1) s += __shfl_xor_sync(0xffffffffu, s, o);
    float mean = s / (float)DM;
    float vs = 0.f;
#pragma unroll
    for (int i = 0; i < DM / 32; i++) { float t = vals[i] - mean; vs += t * t; }
#pragma unroll
    for (int o = 16; o > 0; o >>= 1) vs += __shfl_xor_sync(0xffffffffu, vs, o);
    float inv = rsqrtf(vs / (float)DM + 1e-5f);
    float* xw = x + (size_t)warp * DM;
#pragma unroll
    for (int i = 0; i < DM / 32; i++) {
        int d = lane + i * 32;
        xw[d] = (vals[i] - mean) * inv * gamma[d] + beta[d];
    }
}

// per-batch prefix sum over durations -> idx[b,t] = source token (or -1)
__global__ void scan_kernel(const int* __restrict__ target, int* __restrict__ idx, int T) {
    __shared__ int sdur[LSEQ];
    __shared__ int soff[LSEQ + 1];
    int b = blockIdx.x;
    int j = threadIdx.x;
    sdur[j] = target[b * LSEQ + j];
    __syncthreads();
    if (j == 0) {
        int acc = 0;
        for (int kk = 0; kk < LSEQ; kk++) { soff[kk] = acc; acc += sdur[kk]; }
        soff[LSEQ] = acc;
    }
    __syncthreads();
    int st = soff[j];
    int en = st + sdur[j];
    for (int t = st; t < en; t++) idx[b * T + t] = j;
    int total = soff[LSEQ];
    for (int t = total + j; t < T; t += LSEQ) idx[b * T + t] = -1;
}

// xd[b,t,:] = (idx>=0 ? xe[b,idx,:] : 0) + pe[b,:]
__global__ void gather_pe_kernel(const float* __restrict__ xe,
                                 const int* __restrict__ idx,
                                 float* __restrict__ xd, int T) {
    size_t i = (size_t)blockIdx.x * blockDim.x + threadIdx.x;
    size_t tot = (size_t)NB * T * DM;
    if (i >= tot) return;
    int d = (int)(i % DM);
    size_t bt = i / DM;
    int b = (int)(bt / T);
    int j = idx[bt];
    float val = (j >= 0) ? xe[((size_t)b * LSEQ + j) * DM + d] : 0.f;
    xd[i] = val + pe_val(b, d);
}

// ---------------- m16n8k16 bf16 mma wrapper ----------------
__device__ __forceinline__ void mma_bf16(float* c, const uint32_t* a, const uint32_t* b) {
    asm volatile(
        "mma.sync.aligned.m16n8k16.row.col.f32.bf16.bf16.f32 "
        "{%0,%1,%2,%3}, {%4,%5,%6,%7}, {%8,%9}, {%0,%1,%2,%3};"
        : "+f"(c[0]), "+f"(c[1]), "+f"(c[2]), "+f"(c[3])
        : "r"(a[0]), "r"(a[1]), "r"(a[2]), "r"(a[3]),
          "r"(b[0]), "r"(b[1]));
}

// ---------------- generic 128x128x16 bf16x3 tensor-core GEMM ----------------
// Error-compensated: x = hi + lo (bf16 split); A@B ~= Ah@Bh + Ah@Bl + Al@Bh.
// mode 0: C = act(A@B + bias)        A(M,K) lda, B(K,N) ldb row-major
// mode 1: scores: per g=blockIdx.z  C[g] = scale * Q[g] @ K[g]^T  (B transposed access)
// mode 2: AV:     per g             C[g](S,DS) = attn[g] @ V[g], strided C (merge heads)
// mode 3: conv3:  C = relu(sum_tap Xshift(tap) @ Wt + bias), K = 3*Cin
// mode 4: qkv:    z selects B/bias/C slice (C stride QKV_STRIDE)
// Software-pipelined: register prefetch of next k-tile overlaps with MMA compute.
// Smem row stride 136 words (mod 32 == 8) -> conflict-free fragment loads.
__global__ void __launch_bounds__(256, 2)
gemm_kernel(int mode,
            const float* __restrict__ A, int lda,
            const float* __restrict__ Bm, int ldb,
            const float* __restrict__ bias,
            float* __restrict__ C, int ldc,
            int M, int N, int K, float scale, int relu,
            int S, int Cin) {
    __shared__ uint32_t As_hi[8][136];
    __shared__ uint32_t As_lo[8][136];
    __shared__ uint32_t Bs_hi[8][136];
    __shared__ uint32_t Bs_lo[8][136];
    int tid = threadIdx.x;
    int row0 = blockIdx.y * 128;
    int col0 = blockIdx.x * 128;
    int g = blockIdx.z;
    if (mode == 1) {
        int b = g >> 1, h = g & 1;
        A  += (size_t)b * S * 384 + h * DS;
        Bm += (size_t)b * S * 384 + h * DS;
        C  += (size_t)g * S * S;
    } else if (mode == 2) {
        int b = g >> 1, h = g & 1;
        A  += (size_t)g * S * S;
        Bm += (size_t)b * S * 384 + h * DS;
        C  += (size_t)b * S * 384 + h * DS;
    } else if (mode == 4) {
        Bm   += (size_t)g * DM * DKK;
        bias += (size_t)g * DKK;
        C    += (size_t)g * QKV_STRIDE;
    }

    int wid  = tid >> 5;
    int lane = tid & 31;
    int wm = (wid & 1) * 64;      // warp row offset within 128
    int wn = (wid >> 1) * 32;     // warp col offset within 128
    int gid = lane >> 2;          // 0..7
    int tig = lane & 3;           // 0..3

    float acc[16][4];             // [i*4+j][c0..c3]
#pragma unroll
    for (int t = 0; t < 16; t++)
#pragma unroll
        for (int c = 0; c < 4; c++) acc[t][c] = 0.f;

    float pa[4][2], pb[4][2];     // prefetch registers

    // ---- tile loaders (into registers) ----
    auto load_A = [&](int k0) {
#pragma unroll
        for (int it = 0; it < 4; it++) {
            int idx = tid + it * 256;          // 0..1023
            int pair = idx & 7;                // k-pair 0..7
            int m = idx >> 3;                  // 0..127
            int r = row0 + m;
            int kg0 = k0 + pair * 2;
            float v0 = 0.f, v1 = 0.f;
            if (mode == 3) {
                if (r < M) {
                    int b = r / S, s = r - b * S;
                    if (kg0 < K) {
                        int tap = kg0 / Cin, d = kg0 - tap * Cin;
                        int ss = s + tap - 1;
                        if (ss >= 0 && ss < S) v0 = A[((size_t)b * S + ss) * Cin + d];
                    }
                    if (kg0 + 1 < K) {
                        int kg1 = kg0 + 1;
                        int tap = kg1 / Cin, d = kg1 - tap * Cin;
                        int ss = s + tap - 1;
                        if (ss >= 0 && ss < S) v1 = A[((size_t)b * S + ss) * Cin + d];
                    }
                }
            } else {
                if (r < M) {
                    const float* ar = A + (size_t)r * lda;
                    if (kg0 < K)     v0 = ar[kg0];
                    if (kg0 + 1 < K) v1 = ar[kg0 + 1];
                }
            }
            pa[it][0] = v0; pa[it][1] = v1;
        }
    };
    auto load_B = [&](int k0) {
        if (mode == 1) {
#pragma unroll
            for (int it = 0; it < 4; it++) {
                int idx = tid + it * 256;
                int pair = idx & 7;
                int n = idx >> 3;
                int c = col0 + n;
                int kg0 = k0 + pair * 2;
                float v0 = 0.f, v1 = 0.f;
                if (c < N) {
                    const float* br = Bm + (size_t)c * ldb;
                    if (kg0 < K)     v0 = br[kg0];
                    if (kg0 + 1 < K) v1 = br[kg0 + 1];
                }
                pb[it][0] = v0; pb[it][1] = v1;
            }
        } else {
#pragma unroll
            for (int it = 0; it < 4; it++) {
                int idx = tid + it * 256;
                int n = idx & 127;
                int pair = idx >> 7;
                int c = col0 + n;
                int kg0 = k0 + pair * 2;
                float v0 = 0.f, v1 = 0.f;
                if (c < N) {
                    if (kg0 < K)     v0 = Bm[(size_t)kg0 * ldb + c];
                    if (kg0 + 1 < K) v1 = Bm[(size_t)(kg0 + 1) * ldb + c];
                }
                pb[it][0] = v0; pb[it][1] = v1;
            }
        }
    };

    // ---- prologue: load k-tile 0 ----
    load_A(0);
    load_B(0);

    for (int k0 = 0; k0 < K; k0 += 16) {
        // ---- store prefetched tile to smem (with bf16 split) ----
#pragma unroll
        for (int it = 0; it < 4; it++) {
            int idx = tid + it * 256;
            int pair = idx & 7;
            int m = idx >> 3;
            split_pack(pa[it][0], pa[it][1], As_hi[pair][m], As_lo[pair][m]);
        }
        if (mode == 1) {
#pragma unroll
            for (int it = 0; it < 4; it++) {
                int idx = tid + it * 256;
                int pair = idx & 7;
                int n = idx >> 3;
                split_pack(pb[it][0], pb[it][1], Bs_hi[pair][n], Bs_lo[pair][n]);
            }
        } else {
#pragma unroll
            for (int it = 0; it < 4; it++) {
                int idx = tid + it * 256;
                int n = idx & 127;
                int pair = idx >> 7;
                split_pack(pb[it][0], pb[it][1], Bs_hi[pair][n], Bs_lo[pair][n]);
            }
        }
        __syncthreads();

        // ---- issue next tile's global loads (latency hidden by MMAs below) ----
        if (k0 + 16 < K) {
            load_A(k0 + 16);
            load_B(k0 + 16);
        }

        // ---- compute: one k16 step, 3 compensated products ----
        {
            uint32_t a_hi[4][4], b_hi[4][2];
#pragma unroll
            for (int i = 0; i < 4; i++) {
                int m0 = wm + i * 16 + gid;
                a_hi[i][0] = As_hi[tig][m0];
                a_hi[i][1] = As_hi[tig][m0 + 8];
                a_hi[i][2] = As_hi[tig + 4][m0];
                a_hi[i][3] = As_hi[tig + 4][m0 + 8];
            }
#pragma unroll
            for (int j = 0; j < 4; j++) {
                int n0 = wn + j * 8 + gid;
                b_hi[j][0] = Bs_hi[tig][n0];
                b_hi[j][1] = Bs_hi[tig + 4][n0];
            }
            // hi * hi
#pragma unroll
            for (int i = 0; i < 4; i++)
#pragma unroll
                for (int j = 0; j < 4; j++)
                    mma_bf16(acc[i * 4 + j], a_hi[i], b_hi[j]);
            // hi * lo
            {
                uint32_t b_lo[4][2];
#pragma unroll
                for (int j = 0; j < 4; j++) {
                    int n0 = wn + j * 8 + gid;
                    b_lo[j][0] = Bs_lo[tig][n0];
                    b_lo[j][1] = Bs_lo[tig + 4][n0];
                }
#pragma unroll
                for (int i = 0; i < 4; i++)
#pragma unroll
                    for (int j = 0; j < 4; j++)
                        mma_bf16(acc[i * 4 + j], a_hi[i], b_lo[j]);
            }
            // lo * hi
            {
                uint32_t a_lo[4][4];
#pragma unroll
                for (int i = 0; i < 4; i++) {
                    int m0 = wm + i * 16 + gid;
                    a_lo[i][0] = As_lo[tig][m0];
                    a_lo[i][1] = As_lo[tig][m0 + 8];
                    a_lo[i][2] = As_lo[tig + 4][m0];
                    a_lo[i][3] = As_lo[tig + 4][m0 + 8];
                }
#pragma unroll
                for (int i = 0; i < 4; i++)
#pragma unroll
                    for (int j = 0; j < 4; j++)
                        mma_bf16(acc[i * 4 + j], a_lo[i], b_hi[j]);
            }
        }
        __syncthreads();
    }

    // ---- epilogue ----
#pragma unroll
    for (int i = 0; i < 4; i++) {
#pragma unroll
        for (int j = 0; j < 4; j++) {
            float* c4 = acc[i * 4 + j];
            int cc = col0 + wn + j * 8 + tig * 2;
#pragma unroll
            for (int half = 0; half < 2; half++) {
                int r = row0 + wm + i * 16 + gid + half * 8;
                if (r >= M) continue;
#pragma unroll
                for (int e = 0; e < 2; e++) {
                    int c = cc + e;
                    if (c >= N) continue;
                    float v = c4[half * 2 + e] * scale;
                    if (bias) v += bias[c];
                    if (relu) v = fmaxf(v, 0.f);
                    C[(size_t)r * ldc + c] = v;
                }
            }
        }
    }
}

// ---------------- host driver ----------------
static inline void launch_gemm(int mode, const float* A, int lda,
                               const float* B, int ldb, const float* bias,
                               float* C, int ldc, int M, int N, int K,
                               float scale, int relu, int S, int Cin, int batch) {
    dim3 grid((N + 127) / 128, (M + 127) / 128, batch);
    gemm_kernel<<<grid, 256>>>(mode, A, lda, B, ldb, bias, C, ldc,
                               M, N, K, scale, relu, S, Cin);
}

extern "C" void kernel_launch(void* const* d_in, const int* in_sizes, int n_in,
                              void* d_out, int out_size) {
    // -------- input pointers (metadata order) --------
    const int*   tokens  = (const int*)d_in[0];
    const int*   target  = (const int*)d_in[1];
    const float* emb     = (const float*)d_in[2];
    const float* s_Wqkv[2] = { (const float*)d_in[3],  (const float*)d_in[13] };
    const float* s_bqkv[2] = { (const float*)d_in[4],  (const float*)d_in[14] };
    const float* s_Wo  [2] = { (const float*)d_in[5],  (const float*)d_in[15] };
    const float* s_bo  [2] = { (const float*)d_in[6],  (const float*)d_in[16] };
    const float* s_ln1 [2] = { (const float*)d_in[7],  (const float*)d_in[17] };
    const float* s_c1w [2] = { (const float*)d_in[8],  (const float*)d_in[18] };
    const float* s_c1b [2] = { (const float*)d_in[9],  (const float*)d_in[19] };
    const float* s_c2w [2] = { (const float*)d_in[10], (const float*)d_in[20] };
    const float* s_c2b [2] = { (const float*)d_in[11], (const float*)d_in[21] };
    const float* s_ln2 [2] = { (const float*)d_in[12], (const float*)d_in[22] };
    const float* head_w  = (const float*)d_in[23];
    const float* head_b  = (const float*)d_in[24];
    float* out = (float*)d_out;

    // -------- scratch pointers --------
    float *x, *x2, *qkv, *z, *tmp, *h, *sc, *c1wT, *c2wT;
    int* idxp;
    cudaGetSymbolAddress((void**)&x,    g_x);
    cudaGetSymbolAddress((void**)&x2,   g_x2);
    cudaGetSymbolAddress((void**)&qkv,  g_qkv);
    cudaGetSymbolAddress((void**)&z,    g_z);
    cudaGetSymbolAddress((void**)&tmp,  g_t);
    cudaGetSymbolAddress((void**)&h,    g_h);
    cudaGetSymbolAddress((void**)&sc,   g_sc);
    cudaGetSymbolAddress((void**)&idxp, g_idx);
    cudaGetSymbolAddress((void**)&c1wT, g_c1wT);
    cudaGetSymbolAddress((void**)&c2wT, g_c2wT);

    float* q = qkv;
    float* k = qkv + QKV_STRIDE;
    float* v = qkv + 2 * QKV_STRIDE;

    const int T = out_size / (NB * MMEL);   // expanded length from output shape

    // -------- weight transposes (conv weights -> (tap,Cin,Cout)) --------
    for (int st = 0; st < 2; st++) {
        transpose_w_kernel<<<2048, 256>>>(s_c1w[st],
            c1wT + (size_t)st * NLAY * 3 * DM * CDIM, CDIM, DM, NLAY);
        transpose_w_kernel<<<2048, 256>>>(s_c2w[st],
            c2wT + (size_t)st * NLAY * 3 * CDIM * DM, DM, CDIM, NLAY);
    }

    // -------- embedding + pe --------
    {
        int tot = NB * LSEQ * DM;
        embed_kernel<<<(tot + 255) / 256, 256>>>(tokens, emb, x);
    }

    const float attn_scale = rsqrtf((float)DS);

    // -------- run a stack (st = 0 enc, 1 dec) --------
    auto run_stack = [&](int st, float* xbuf, int S) {
        int Mr = NB * S;
        for (int l = 0; l < NLAY; l++) {
            const float* Wqkv = s_Wqkv[st] + (size_t)l * 3 * DM * DKK;
            const float* bqkv = s_bqkv[st] + (size_t)l * 3 * DKK;
            // q,k,v = relu(x @ Wqkv_t + b_t)  — single z=3 launch
            launch_gemm(4, xbuf, DM, Wqkv, DKK, bqkv,
                        qkv, DKK, Mr, DKK, DM, 1.f, 1, 0, 0, 3);
            // scores[g] = scale * q[g] @ k[g]^T
            launch_gemm(1, q, 384, k, 384, nullptr, sc, S,
                        S, S, DS, attn_scale, 0, S, 0, NB * NH);
            // softmax over g
            {
                size_t tot = (size_t)S * S;
                softmax_g_kernel<<<(unsigned)((tot + 255) / 256), 256>>>(sc, S);
            }
            // z[g] = attn[g] @ v[g]  (written merged into (B,S,384))
            launch_gemm(2, sc, S, v, 384, nullptr, z, 384,
                        S, DS, S, 1.f, 0, S, 0, NB * NH);
            // tmp = relu(z @ Wo + bo)
            launch_gemm(0, z, DKK, s_Wo[st] + (size_t)l * DKK * DM, DM,
                        s_bo[st] + (size_t)l * DM, tmp, DM,
                        Mr, DM, DKK, 1.f, 1, 0, 0, 1);
            // x = LN(x + tmp)
            ln_res_kernel<<<(Mr + 7) / 8, 256>>>(xbuf, tmp,
                s_ln1[st] + (size_t)(l * 2 + 0) * DM,
                s_ln1[st] + (size_t)(l * 2 + 1) * DM, Mr);
            // h = relu(conv1(x))
            launch_gemm(3, xbuf, DM,
                        c1wT + ((size_t)st * NLAY + l) * 3 * DM * CDIM, CDIM,
                        s_c1b[st] + (size_t)l * CDIM, h, CDIM,
                        Mr, CDIM, 3 * DM, 1.f, 1, S, DM, 1);
            // tmp = relu(conv2(h))
            launch_gemm(3, h, CDIM,
                        c2wT + ((size_t)st * NLAY + l) * 3 * CDIM * DM, DM,
                        s_c2b[st] + (size_t)l * DM, tmp, DM,
                        Mr, DM, 3 * CDIM, 1.f, 1, S, CDIM, 1);
            // x = LN(x + tmp)
            ln_res_kernel<<<(Mr + 7) / 8, 256>>>(xbuf, tmp,
                s_ln2[st] + (size_t)(l * 2 + 0) * DM,
                s_ln2[st] + (size_t)(l * 2 + 1) * DM, Mr);
        }
    };

    // encoder
    run_stack(0, x, LSEQ);

    // length regulator + pe
    scan_kernel<<<NB, LSEQ>>>(target, idxp, T);
    {
        size_t tot = (size_t)NB * T * DM;
        gather_pe_kernel<<<(unsigned)((tot + 255) / 256), 256>>>(x, idxp, x2, T);
    }

    // decoder
    run_stack(1, x2, T);

    // mel head: out = x2 @ head_w + head_b
    launch_gemm(0, x2, DM, head_w, MMEL, head_b, out, MMEL,
                NB * T, MMEL, DM, 1.f, 0, 0, 0, 1);
}

// round 17
// speedup vs baseline: 2.2185x; 1.2786x over previous
#include <cuda_runtime.h>
#include <cuda_bf16.h>
#include <math.h>
#include <stdint.h>
#include <stddef.h>

// ---------------- problem constants ----------------
constexpr int NB   = 8;     // batch
constexpr int LSEQ = 256;   // encoder seq len
constexpr int NLAY = 4;     // layers per stack
constexpr int DM   = 384;   // model dim
constexpr int DKK  = 384;   // qkv dim
constexpr int NH   = 2;     // heads
constexpr int DS   = 192;   // head dim
constexpr int CDIM = 1536;  // conv hidden
constexpr int MMEL = 80;    // mel bins
constexpr int TMAX = 3840;  // max expanded length
constexpr long RMAX = (long)NB * TMAX;   // 30720 max rows

// ---------------- static scratch (zero-initialized at load; pads stay 0) ----
// activations as bf16 hi/lo pairs
__device__ __nv_bfloat16 g_x_h [RMAX * DM],   g_x_l [RMAX * DM];
__device__ __nv_bfloat16 g_x2_h[RMAX * DM],   g_x2_l[RMAX * DM];
__device__ __nv_bfloat16 g_q_h [RMAX * DKK],  g_q_l [RMAX * DKK];
__device__ __nv_bfloat16 g_k_h [RMAX * DKK],  g_k_l [RMAX * DKK];
__device__ __nv_bfloat16 g_vT_h[RMAX * DKK],  g_vT_l[RMAX * DKK];  // [b][dk][s]
__device__ __nv_bfloat16 g_z_h [RMAX * DKK],  g_z_l [RMAX * DKK];
__device__ __nv_bfloat16 g_h_h [RMAX * CDIM], g_h_l [RMAX * CDIM];
__device__ __nv_bfloat16 g_sc_h[(size_t)NB * NH * TMAX * TMAX];
__device__ __nv_bfloat16 g_sc_l[(size_t)NB * NH * TMAX * TMAX];
__device__ float g_t  [RMAX * DM];             // f32 temp for residual adds
__device__ int   g_idx[RMAX];
// pre-split bf16 weights, [N][K] k-major (hi/lo)
__device__ __nv_bfloat16 g_wqkv_h[2 * NLAY * 3 * DM * DKK];
__device__ __nv_bfloat16 g_wqkv_l[2 * NLAY * 3 * DM * DKK];
__device__ __nv_bfloat16 g_wo_h  [2 * NLAY * DKK * DM];
__device__ __nv_bfloat16 g_wo_l  [2 * NLAY * DKK * DM];
__device__ __nv_bfloat16 g_c1_h  [2 * NLAY * CDIM * 3 * DM];
__device__ __nv_bfloat16 g_c1_l  [2 * NLAY * CDIM * 3 * DM];
__device__ __nv_bfloat16 g_c2_h  [2 * NLAY * DM * 3 * CDIM];
__device__ __nv_bfloat16 g_c2_l  [2 * NLAY * DM * 3 * CDIM];
__device__ __nv_bfloat16 g_head_h[MMEL * DM];
__device__ __nv_bfloat16 g_head_l[MMEL * DM];

// ---------------- helpers ----------------
__device__ __forceinline__ float pe_val(int b, int d) {
    int i2 = (d >> 1) << 1;
    float div = expf(-(float)i2 * (9.210340371976184f / (float)DM));
    float ang = (float)b * div;
    return (d & 1) ? cosf(ang) : sinf(ang);
}

__device__ __forceinline__ void split1(float v, __nv_bfloat16& h, __nv_bfloat16& l) {
    h = __float2bfloat16(v);
    l = __float2bfloat16(v - __bfloat162float(h));
}

__device__ __forceinline__ uint32_t pack2(__nv_bfloat16 a, __nv_bfloat16 b) {
    __nv_bfloat162 p; p.x = a; p.y = b;
    return *reinterpret_cast<uint32_t*>(&p);
}

// ---------------- m16n8k16 bf16 mma wrapper ----------------
__device__ __forceinline__ void mma_bf16(float* c, const uint32_t* a, const uint32_t* b) {
    asm volatile(
        "mma.sync.aligned.m16n8k16.row.col.f32.bf16.bf16.f32 "
        "{%0,%1,%2,%3}, {%4,%5,%6,%7}, {%8,%9}, {%0,%1,%2,%3};"
        : "+f"(c[0]), "+f"(c[1]), "+f"(c[2]), "+f"(c[3])
        : "r"(a[0]), "r"(a[1]), "r"(a[2]), "r"(a[3]),
          "r"(b[0]), "r"(b[1]));
}

// ---------------- elementwise kernels ----------------
__global__ void embed_kernel(const int* __restrict__ tokens,
                             const float* __restrict__ emb,
                             __nv_bfloat16* __restrict__ xh,
                             __nv_bfloat16* __restrict__ xl) {
    int i = blockIdx.x * blockDim.x + threadIdx.x;
    const int tot = NB * LSEQ * DM;
    if (i >= tot) return;
    int d  = i % DM;
    int bs = i / DM;
    int b  = bs / LSEQ;
    int tok = tokens[bs];
    float v = emb[tok * DM + d] + pe_val(b, d);
    split1(v, xh[i], xl[i]);
}

// W (mats, K, N) f32 -> Wh/Wl (mats, N, K) bf16
__global__ void split_wT_kernel(const float* __restrict__ w,
                                __nv_bfloat16* __restrict__ wh,
                                __nv_bfloat16* __restrict__ wl,
                                int K, int N, int mats) {
    size_t tot = (size_t)mats * K * N;
    for (size_t idx = (size_t)blockIdx.x * blockDim.x + threadIdx.x;
         idx < tot; idx += (size_t)gridDim.x * blockDim.x) {
        int n = (int)(idx % N);
        size_t r = idx / N;
        int k = (int)(r % K);
        int m = (int)(r / K);
        size_t o = ((size_t)m * N + n) * K + k;
        split1(w[idx], wh[o], wl[o]);
    }
}

// conv w (L, Cout, Cin, 3) -> (L, Cout, 3*Cin) k-major, k = tap*Cin + d
__global__ void split_conv_kernel(const float* __restrict__ w,
                                  __nv_bfloat16* __restrict__ wh,
                                  __nv_bfloat16* __restrict__ wl,
                                  int Cout, int Cin, int L) {
    size_t tot = (size_t)L * Cout * Cin * 3;
    for (size_t idx = (size_t)blockIdx.x * blockDim.x + threadIdx.x;
         idx < tot; idx += (size_t)gridDim.x * blockDim.x) {
        int t = (int)(idx % 3);
        size_t r = idx / 3;
        int d = (int)(r % Cin);
        size_t r2 = r / Cin;
        int c = (int)(r2 % Cout);
        int l = (int)(r2 / Cout);
        size_t o = (((size_t)l * Cout + c) * 3 + t) * Cin + d;
        split1(w[idx], wh[o], wl[o]);
    }
}

// softmax across the 16 (B*H) slices; sc rows strided Spad, split storage
__global__ void softmax_g_kernel(__nv_bfloat16* __restrict__ sch,
                                 __nv_bfloat16* __restrict__ scl,
                                 int S, int Spad) {
    size_t ij = (size_t)blockIdx.x * blockDim.x + threadIdx.x;
    size_t tot = (size_t)S * S;
    if (ij >= tot) return;
    int i = (int)(ij / S), j = (int)(ij % S);
    size_t gsz = (size_t)S * Spad;
    size_t off = (size_t)i * Spad + j;
    float v[NB * NH];
    float m = -1e30f;
#pragma unroll
    for (int g = 0; g < NB * NH; g++) {
        size_t o = (size_t)g * gsz + off;
        v[g] = __bfloat162float(sch[o]) + __bfloat162float(scl[o]);
        m = fmaxf(m, v[g]);
    }
    float s = 0.f;
#pragma unroll
    for (int g = 0; g < NB * NH; g++) { v[g] = expf(v[g] - m); s += v[g]; }
    float inv = 1.f / s;
#pragma unroll
    for (int g = 0; g < NB * NH; g++) {
        size_t o = (size_t)g * gsz + off;
        split1(v[g] * inv, sch[o], scl[o]);
    }
}

// x = LayerNorm((xh+xl) + y) -> split back into xh/xl
__global__ void ln_res_kernel(__nv_bfloat16* __restrict__ xh,
                              __nv_bfloat16* __restrict__ xl,
                              const float* __restrict__ y,
                              const float* __restrict__ gamma,
                              const float* __restrict__ beta, int Mrows) {
    int warp = (blockIdx.x * blockDim.x + threadIdx.x) >> 5;
    int lane = threadIdx.x & 31;
    if (warp >= Mrows) return;
    size_t base = (size_t)warp * DM;
    float vals[DM / 32];
    float s = 0.f;
#pragma unroll
    for (int i = 0; i < DM / 32; i++) {
        int d = lane + i * 32;
        vals[i] = __bfloat162float(xh[base + d]) + __bfloat162float(xl[base + d])
                + y[base + d];
        s += vals[i];
    }
#pragma unroll
    for (int o = 16; o > 0; o >>= 1) s += __shfl_xor_sync(0xffffffffu, s, o);
    float mean = s / (float)DM;
    float vs = 0.f;
#pragma unroll
    for (int i = 0; i < DM / 32; i++) { float t = vals[i] - mean; vs += t * t; }
#pragma unroll
    for (int o = 16; o > 0; o >>= 1) vs += __shfl_xor_sync(0xffffffffu, vs, o);
    float inv = rsqrtf(vs / (float)DM + 1e-5f);
#pragma unroll
    for (int i = 0; i < DM / 32; i++) {
        int d = lane + i * 32;
        float v = (vals[i] - mean) * inv * gamma[d] + beta[d];
        split1(v, xh[base + d], xl[base + d]);
    }
}

__global__ void scan_kernel(const int* __restrict__ target, int* __restrict__ idx, int T) {
    __shared__ int sdur[LSEQ];
    __shared__ int soff[LSEQ + 1];
    int b = blockIdx.x;
    int j = threadIdx.x;
    sdur[j] = target[b * LSEQ + j];
    __syncthreads();
    if (j == 0) {
        int acc = 0;
        for (int kk = 0; kk < LSEQ; kk++) { soff[kk] = acc; acc += sdur[kk]; }
        soff[LSEQ] = acc;
    }
    __syncthreads();
    int st = soff[j];
    int en = st + sdur[j];
    for (int t = st; t < en; t++) idx[b * T + t] = j;
    int total = soff[LSEQ];
    for (int t = total + j; t < T; t += LSEQ) idx[b * T + t] = -1;
}

__global__ void gather_pe_kernel(const __nv_bfloat16* __restrict__ xeh,
                                 const __nv_bfloat16* __restrict__ xel,
                                 const int* __restrict__ idx,
                                 __nv_bfloat16* __restrict__ xdh,
                                 __nv_bfloat16* __restrict__ xdl, int T) {
    size_t i = (size_t)blockIdx.x * blockDim.x + threadIdx.x;
    size_t tot = (size_t)NB * T * DM;
    if (i >= tot) return;
    int d = (int)(i % DM);
    size_t bt = i / DM;
    int b = (int)(bt / T);
    int j = idx[bt];
    float val = 0.f;
    if (j >= 0) {
        size_t o = ((size_t)b * LSEQ + j) * DM + d;
        val = __bfloat162float(xeh[o]) + __bfloat162float(xel[o]);
    }
    split1(val + pe_val(b, d), xdh[i], xdl[i]);
}

// ---------------- 128x128x16 bf16x3 tensor-core GEMM, pre-split operands ----
// All operands are k-major bf16 hi/lo pairs: X[row][k].
// mode 0: plain           A(M,K) lda / B(N,K) ldb
// mode 1: scores QK^T     per g: A=q,B=k slices; C=sc split, ldc=Spad, pad-zeroed
// mode 2: AV              per g: A=attn (lda=Spad, K=Spad), B=vT slice; C=z split
// mode 3: conv3 gather A  (K=3*Cin)
// mode 4: qkv             B/bias slice g; g<2 -> q/k split; g==2 -> vT transposed
__global__ void __launch_bounds__(256, 2)
mma_gemm(int mode,
         const __nv_bfloat16* __restrict__ Ah,
         const __nv_bfloat16* __restrict__ Al, int lda,
         const __nv_bfloat16* __restrict__ Bh,
         const __nv_bfloat16* __restrict__ Bl, int ldb,
         const float* __restrict__ bias,
         float* __restrict__ Cf,
         __nv_bfloat16* __restrict__ Ch,
         __nv_bfloat16* __restrict__ Cl, int ldc,
         int M, int N, int K, int Npad,
         float scale, int relu, int S, int Spad, int Cin) {
    __shared__ uint32_t As_hi[8][136];
    __shared__ uint32_t As_lo[8][136];
    __shared__ uint32_t Bs_hi[8][136];
    __shared__ uint32_t Bs_lo[8][136];
    int tid = threadIdx.x;
    int row0 = blockIdx.y * 128;
    int col0 = blockIdx.x * 128;
    int g = blockIdx.z;
    bool vt_out = false;

    if (mode == 1) {
        int b = g >> 1, h = g & 1;
        size_t ao = (size_t)b * S * 384 + h * DS;
        Ah += ao; Al += ao; Bh += ao; Bl += ao;
        size_t co = (size_t)g * S * Spad;
        Ch += co; Cl += co;
    } else if (mode == 2) {
        int b = g >> 1, h = g & 1;
        size_t ao = (size_t)g * S * Spad;
        Ah += ao; Al += ao;
        size_t bo = ((size_t)b * 384 + h * DS) * Spad;
        Bh += bo; Bl += bo;
        size_t co = (size_t)b * S * 384 + h * DS;
        Ch += co; Cl += co;
    } else if (mode == 4) {
        size_t bo = (size_t)g * DM * DKK;
        Bh += bo; Bl += bo;
        bias += (size_t)g * DKK;
        if (g == 0)      { Ch = &g_q_h[0]; Cl = &g_q_l[0]; }
        else if (g == 1) { Ch = &g_k_h[0]; Cl = &g_k_l[0]; }
        else             { vt_out = true; }
    }

    int wid  = tid >> 5;
    int lane = tid & 31;
    int wm = (wid & 1) * 64;
    int wn = (wid >> 1) * 32;
    int gid = lane >> 2;
    int tig = lane & 3;

    float acc[16][4];
#pragma unroll
    for (int t = 0; t < 16; t++)
#pragma unroll
        for (int c = 0; c < 4; c++) acc[t][c] = 0.f;

    uint32_t pah[4], pal[4], pbh[4], pbl[4];

    auto load_A = [&](int k0) {
#pragma unroll
        for (int it = 0; it < 4; it++) {
            int idx = tid + it * 256;
            int pair = idx & 7;
            int m = idx >> 3;
            int r = row0 + m;
            int kg0 = k0 + pair * 2;
            uint32_t h = 0, l = 0;
            if (mode == 3) {
                if (r < M && kg0 < K) {
                    int b = r / S, s = r - b * S;
                    int tap = kg0 / Cin, d = kg0 - tap * Cin;
                    int ss = s + tap - 1;
                    if (ss >= 0 && ss < S) {
                        size_t o = ((size_t)b * S + ss) * Cin + d;
                        h = *reinterpret_cast<const uint32_t*>(Ah + o);
                        l = *reinterpret_cast<const uint32_t*>(Al + o);
                    }
                }
            } else {
                if (r < M && kg0 < K) {
                    size_t o = (size_t)r * lda + kg0;
                    h = *reinterpret_cast<const uint32_t*>(Ah + o);
                    l = *reinterpret_cast<const uint32_t*>(Al + o);
                }
            }
            pah[it] = h; pal[it] = l;
        }
    };
    auto load_B = [&](int k0) {
#pragma unroll
        for (int it = 0; it < 4; it++) {
            int idx = tid + it * 256;
            int pair = idx & 7;
            int n = idx >> 3;
            int c = col0 + n;
            int kg0 = k0 + pair * 2;
            uint32_t h = 0, l = 0;
            if (c < N && kg0 < K) {
                size_t o = (size_t)c * ldb + kg0;
                h = *reinterpret_cast<const uint32_t*>(Bh + o);
                l = *reinterpret_cast<const uint32_t*>(Bl + o);
            }
            pbh[it] = h; pbl[it] = l;
        }
    };

    load_A(0);
    load_B(0);

    for (int k0 = 0; k0 < K; k0 += 16) {
        // ---- store prefetched tile to smem ----
#pragma unroll
        for (int it = 0; it < 4; it++) {
            int idx = tid + it * 256;
            int pair = idx & 7;
            int m = idx >> 3;
            As_hi[pair][m] = pah[it];
            As_lo[pair][m] = pal[it];
            Bs_hi[pair][m] = pbh[it];
            Bs_lo[pair][m] = pbl[it];
        }
        __syncthreads();

        // ---- issue next tile's global loads ----
        if (k0 + 16 < K) {
            load_A(k0 + 16);
            load_B(k0 + 16);
        }

        // ---- compute: 3 compensated products ----
        {
            uint32_t a_hi[4][4], b_hi[4][2];
#pragma unroll
            for (int i = 0; i < 4; i++) {
                int m0 = wm + i * 16 + gid;
                a_hi[i][0] = As_hi[tig][m0];
                a_hi[i][1] = As_hi[tig][m0 + 8];
                a_hi[i][2] = As_hi[tig + 4][m0];
                a_hi[i][3] = As_hi[tig + 4][m0 + 8];
            }
#pragma unroll
            for (int j = 0; j < 4; j++) {
                int n0 = wn + j * 8 + gid;
                b_hi[j][0] = Bs_hi[tig][n0];
                b_hi[j][1] = Bs_hi[tig + 4][n0];
            }
#pragma unroll
            for (int i = 0; i < 4; i++)
#pragma unroll
                for (int j = 0; j < 4; j++)
                    mma_bf16(acc[i * 4 + j], a_hi[i], b_hi[j]);
            {
                uint32_t b_lo[4][2];
#pragma unroll
                for (int j = 0; j < 4; j++) {
                    int n0 = wn + j * 8 + gid;
                    b_lo[j][0] = Bs_lo[tig][n0];
                    b_lo[j][1] = Bs_lo[tig + 4][n0];
                }
#pragma unroll
                for (int i = 0; i < 4; i++)
#pragma unroll
                    for (int j = 0; j < 4; j++)
                        mma_bf16(acc[i * 4 + j], a_hi[i], b_lo[j]);
            }
            {
                uint32_t a_lo[4][4];
#pragma unroll
                for (int i = 0; i < 4; i++) {
                    int m0 = wm + i * 16 + gid;
                    a_lo[i][0] = As_lo[tig][m0];
                    a_lo[i][1] = As_lo[tig][m0 + 8];
                    a_lo[i][2] = As_lo[tig + 4][m0];
                    a_lo[i][3] = As_lo[tig + 4][m0 + 8];
                }
#pragma unroll
                for (int i = 0; i < 4; i++)
#pragma unroll
                    for (int j = 0; j < 4; j++)
                        mma_bf16(acc[i * 4 + j], a_lo[i], b_hi[j]);
            }
        }
        __syncthreads();
    }

    // ---- epilogue ----
#pragma unroll
    for (int i = 0; i < 4; i++) {
#pragma unroll
        for (int half = 0; half < 2; half++) {
            int r = row0 + wm + i * 16 + gid + half * 8;
            if (r >= M) continue;
#pragma unroll
            for (int j = 0; j < 4; j++) {
                float* c4 = acc[i * 4 + j];
                int cc = col0 + wn + j * 8 + tig * 2;
                float v0 = c4[half * 2 + 0] * scale;
                float v1 = c4[half * 2 + 1] * scale;
                if (bias) {
                    if (cc < N)     v0 += bias[cc];
                    if (cc + 1 < N) v1 += bias[cc + 1];
                }
                if (relu) { v0 = fmaxf(v0, 0.f); v1 = fmaxf(v1, 0.f); }
                if (cc >= N)     v0 = 0.f;
                if (cc + 1 >= N) v1 = 0.f;
                if (vt_out) {
                    int b = r / S, s = r - b * S;
                    if (cc < N) {
                        __nv_bfloat16 h, l; split1(v0, h, l);
                        size_t o = ((size_t)b * 384 + cc) * Spad + s;
                        g_vT_h[o] = h; g_vT_l[o] = l;
                    }
                    if (cc + 1 < N) {
                        __nv_bfloat16 h, l; split1(v1, h, l);
                        size_t o = ((size_t)b * 384 + cc + 1) * Spad + s;
                        g_vT_h[o] = h; g_vT_l[o] = l;
                    }
                } else if (Ch) {
                    if (cc + 1 < Npad) {
                        __nv_bfloat16 h0, l0, h1, l1;
                        split1(v0, h0, l0); split1(v1, h1, l1);
                        size_t o = (size_t)r * ldc + cc;
                        *reinterpret_cast<uint32_t*>(Ch + o) = pack2(h0, h1);
                        *reinterpret_cast<uint32_t*>(Cl + o) = pack2(l0, l1);
                    } else if (cc < Npad) {
                        __nv_bfloat16 h, l; split1(v0, h, l);
                        size_t o = (size_t)r * ldc + cc;
                        Ch[o] = h; Cl[o] = l;
                    }
                } else {
                    if (cc < N)     Cf[(size_t)r * ldc + cc]     = v0;
                    if (cc + 1 < N) Cf[(size_t)r * ldc + cc + 1] = v1;
                }
            }
        }
    }
}

// ---------------- host driver ----------------
static inline void launch_mm(int mode,
                             const __nv_bfloat16* Ah, const __nv_bfloat16* Al, int lda,
                             const __nv_bfloat16* Bh, const __nv_bfloat16* Bl, int ldb,
                             const float* bias,
                             float* Cf, __nv_bfloat16* Ch, __nv_bfloat16* Cl, int ldc,
                             int M, int N, int K, int Npad,
                             float scale, int relu, int S, int Spad, int Cin,
                             int batch) {
    dim3 grid((N + 127) / 128, (M + 127) / 128, batch);
    mma_gemm<<<grid, 256>>>(mode, Ah, Al, lda, Bh, Bl, ldb, bias,
                            Cf, Ch, Cl, ldc, M, N, K, Npad,
                            scale, relu, S, Spad, Cin);
}

extern "C" void kernel_launch(void* const* d_in, const int* in_sizes, int n_in,
                              void* d_out, int out_size) {
    const int*   tokens  = (const int*)d_in[0];
    const int*   target  = (const int*)d_in[1];
    const float* emb     = (const float*)d_in[2];
    const float* s_Wqkv[2] = { (const float*)d_in[3],  (const float*)d_in[13] };
    const float* s_bqkv[2] = { (const float*)d_in[4],  (const float*)d_in[14] };
    const float* s_Wo  [2] = { (const float*)d_in[5],  (const float*)d_in[15] };
    const float* s_bo  [2] = { (const float*)d_in[6],  (const float*)d_in[16] };
    const float* s_ln1 [2] = { (const float*)d_in[7],  (const float*)d_in[17] };
    const float* s_c1w [2] = { (const float*)d_in[8],  (const float*)d_in[18] };
    const float* s_c1b [2] = { (const float*)d_in[9],  (const float*)d_in[19] };
    const float* s_c2w [2] = { (const float*)d_in[10], (const float*)d_in[20] };
    const float* s_c2b [2] = { (const float*)d_in[11], (const float*)d_in[21] };
    const float* s_ln2 [2] = { (const float*)d_in[12], (const float*)d_in[22] };
    const float* head_w  = (const float*)d_in[23];
    const float* head_b  = (const float*)d_in[24];
    float* out = (float*)d_out;

    __nv_bfloat16 *xh, *xl, *x2h, *x2l, *qh, *ql, *kh, *kl, *vth, *vtl;
    __nv_bfloat16 *zh, *zl, *hh, *hl, *sch, *scl;
    __nv_bfloat16 *wqh, *wql, *woh, *wol, *c1h, *c1l, *c2h, *c2l, *hdh, *hdl;
    float *tmp;
    int* idxp;
    cudaGetSymbolAddress((void**)&xh,   g_x_h);  cudaGetSymbolAddress((void**)&xl,  g_x_l);
    cudaGetSymbolAddress((void**)&x2h,  g_x2_h); cudaGetSymbolAddress((void**)&x2l, g_x2_l);
    cudaGetSymbolAddress((void**)&qh,   g_q_h);  cudaGetSymbolAddress((void**)&ql,  g_q_l);
    cudaGetSymbolAddress((void**)&kh,   g_k_h);  cudaGetSymbolAddress((void**)&kl,  g_k_l);
    cudaGetSymbolAddress((void**)&vth,  g_vT_h); cudaGetSymbolAddress((void**)&vtl, g_vT_l);
    cudaGetSymbolAddress((void**)&zh,   g_z_h);  cudaGetSymbolAddress((void**)&zl,  g_z_l);
    cudaGetSymbolAddress((void**)&hh,   g_h_h);  cudaGetSymbolAddress((void**)&hl,  g_h_l);
    cudaGetSymbolAddress((void**)&sch,  g_sc_h); cudaGetSymbolAddress((void**)&scl, g_sc_l);
    cudaGetSymbolAddress((void**)&tmp,  g_t);
    cudaGetSymbolAddress((void**)&idxp, g_idx);
    cudaGetSymbolAddress((void**)&wqh,  g_wqkv_h); cudaGetSymbolAddress((void**)&wql, g_wqkv_l);
    cudaGetSymbolAddress((void**)&woh,  g_wo_h);   cudaGetSymbolAddress((void**)&wol, g_wo_l);
    cudaGetSymbolAddress((void**)&c1h,  g_c1_h);   cudaGetSymbolAddress((void**)&c1l, g_c1_l);
    cudaGetSymbolAddress((void**)&c2h,  g_c2_h);   cudaGetSymbolAddress((void**)&c2l, g_c2_l);
    cudaGetSymbolAddress((void**)&hdh,  g_head_h); cudaGetSymbolAddress((void**)&hdl, g_head_l);

    const int T = out_size / (NB * MMEL);

    // -------- weight pre-split/transpose --------
    for (int st = 0; st < 2; st++) {
        split_wT_kernel<<<2048, 256>>>(s_Wqkv[st],
            wqh + (size_t)st * NLAY * 3 * DM * DKK,
            wql + (size_t)st * NLAY * 3 * DM * DKK, DM, DKK, NLAY * 3);
        split_wT_kernel<<<2048, 256>>>(s_Wo[st],
            woh + (size_t)st * NLAY * DKK * DM,
            wol + (size_t)st * NLAY * DKK * DM, DKK, DM, NLAY);
        split_conv_kernel<<<4096, 256>>>(s_c1w[st],
            c1h + (size_t)st * NLAY * CDIM * 3 * DM,
            c1l + (size_t)st * NLAY * CDIM * 3 * DM, CDIM, DM, NLAY);
        split_conv_kernel<<<4096, 256>>>(s_c2w[st],
            c2h + (size_t)st * NLAY * DM * 3 * CDIM,
            c2l + (size_t)st * NLAY * DM * 3 * CDIM, DM, CDIM, NLAY);
    }
    split_wT_kernel<<<256, 256>>>(head_w, hdh, hdl, DM, MMEL, 1);

    // -------- embedding + pe --------
    {
        int tot = NB * LSEQ * DM;
        embed_kernel<<<(tot + 255) / 256, 256>>>(tokens, emb, xh, xl);
    }

    const float attn_scale = rsqrtf((float)DS);

    auto run_stack = [&](int st, __nv_bfloat16* bxh, __nv_bfloat16* bxl, int S) {
        int Mr = NB * S;
        int Spad = (S + 15) & ~15;
        for (int l = 0; l < NLAY; l++) {
            const __nv_bfloat16* wq_h = wqh + (size_t)(st * NLAY + l) * 3 * DM * DKK;
            const __nv_bfloat16* wq_l = wql + (size_t)(st * NLAY + l) * 3 * DM * DKK;
            const float* bqkv = s_bqkv[st] + (size_t)l * 3 * DKK;
            // q,k = relu(x@Wq/Wk+b) split; v slice lands transposed in vT split
            launch_mm(4, bxh, bxl, DM, wq_h, wq_l, DM, bqkv,
                      nullptr, nullptr, nullptr, DKK,
                      Mr, DKK, DM, DKK, 1.f, 1, S, Spad, 0, 3);
            // sc[g] = scale * q[g] @ k[g]^T  (split out, pad-zeroed to Spad)
            launch_mm(1, qh, ql, 384, kh, kl, 384, nullptr,
                      nullptr, sch, scl, Spad,
                      S, S, DS, Spad, attn_scale, 0, S, Spad, 0, NB * NH);
            {
                size_t tot = (size_t)S * S;
                softmax_g_kernel<<<(unsigned)((tot + 255) / 256), 256>>>(sch, scl, S, Spad);
            }
            // z[g] = attn[g] @ v[g]  (K runs over padded keys; pads are zero)
            launch_mm(2, sch, scl, Spad, vth, vtl, Spad, nullptr,
                      nullptr, zh, zl, 384,
                      S, DS, Spad, DS, 1.f, 0, S, Spad, 0, NB * NH);
            // tmp = relu(z @ Wo + bo)  (f32 out)
            launch_mm(0, zh, zl, DKK,
                      woh + (size_t)(st * NLAY + l) * DKK * DM,
                      wol + (size_t)(st * NLAY + l) * DKK * DM, DKK,
                      s_bo[st] + (size_t)l * DM,
                      tmp, nullptr, nullptr, DM,
                      Mr, DM, DKK, DM, 1.f, 1, S, Spad, 0, 1);
            ln_res_kernel<<<(Mr + 7) / 8, 256>>>(bxh, bxl, tmp,
                s_ln1[st] + (size_t)(l * 2 + 0) * DM,
                s_ln1[st] + (size_t)(l * 2 + 1) * DM, Mr);
            // h = relu(conv1(x)) split
            launch_mm(3, bxh, bxl, DM,
                      c1h + (size_t)(st * NLAY + l) * CDIM * 3 * DM,
                      c1l + (size_t)(st * NLAY + l) * CDIM * 3 * DM, 3 * DM,
                      s_c1b[st] + (size_t)l * CDIM,
                      nullptr, hh, hl, CDIM,
                      Mr, CDIM, 3 * DM, CDIM, 1.f, 1, S, Spad, DM, 1);
            // tmp = relu(conv2(h)) f32
            launch_mm(3, hh, hl, CDIM,
                      c2h + (size_t)(st * NLAY + l) * DM * 3 * CDIM,
                      c2l + (size_t)(st * NLAY + l) * DM * 3 * CDIM, 3 * CDIM,
                      s_c2b[st] + (size_t)l * DM,
                      tmp, nullptr, nullptr, DM,
                      Mr, DM, 3 * CDIM, DM, 1.f, 1, S, Spad, CDIM, 1);
            ln_res_kernel<<<(Mr + 7) / 8, 256>>>(bxh, bxl, tmp,
                s_ln2[st] + (size_t)(l * 2 + 0) * DM,
                s_ln2[st] + (size_t)(l * 2 + 1) * DM, Mr);
        }
    };

    run_stack(0, xh, xl, LSEQ);

    scan_kernel<<<NB, LSEQ>>>(target, idxp, T);
    {
        size_t tot = (size_t)NB * T * DM;
        gather_pe_kernel<<<(unsigned)((tot + 255) / 256), 256>>>(xh, xl, idxp,
                                                                 x2h, x2l, T);
    }

    run_stack(1, x2h, x2l, T);

    // mel head: out = x2 @ head_w + head_b  (f32 out)
    launch_mm(0, x2h, x2l, DM, hdh, hdl, DM, head_b,
              out, nullptr, nullptr, MMEL,
              NB * T, MMEL, DM, MMEL, 1.f, 0, T, 0, 0, 1);
}